// round 15
// baseline (speedup 1.0000x reference)
#include <cuda_runtime.h>
#include <math.h>
#include <cstdint>

#define B 8
#define NPIX 4096
#define C 512
#define HEADS 16
#define HD 32

// ---------------- scratch (device globals; no runtime allocation) ----------
__device__ float g_qn[B*C*NPIX];        // q projection, (b,c,n) layout
__device__ float g_kn[B*C*NPIX];        // k projection, (b,c,n) layout
__device__ float g_gate[2*B*NPIX];      // spatial gate (sigmoid), q then k
__device__ float g_gpart[16*B*NPIX];    // gate partials: (which*8+cb, b, pix)
__device__ float g_pool[2*B*C];
__device__ float g_cs[2*B*C];           // channel gate (q then k)
__device__ float g_cosT[256*NPIX];      // rope cos, (j, n) layout
__device__ float g_sinT[256*NPIX];
__device__ float g_kv[B*HEADS*HD*HD];
__device__ float g_km[B*HEADS*HD];
__device__ float g_fw[2*C*9];           // folded dwconv weights (w * bn_scale)
__device__ float g_fb[2*C];             // folded bias
// tf32 2-way split of the K half of qk_w (rows 512..1023)
__device__ __align__(16) float g_wa[C*C];
__device__ __align__(16) float g_wb[C*C];

__device__ __forceinline__ float acc_sigmoid(float x) {
    return 1.0f / (1.0f + expf(-x));
}
__device__ __forceinline__ float elu1(float x) {
    return x > 0.0f ? x + 1.0f : expf(x);
}
__device__ __forceinline__ float tf32mask(float v) {
    return __uint_as_float(__float_as_uint(v) & 0xFFFFE000u);
}
__device__ __forceinline__ void mma8(float* c, const uint32_t* a, const uint32_t* b) {
    asm volatile("mma.sync.aligned.m16n8k8.row.col.f32.tf32.tf32.f32 "
        "{%0,%1,%2,%3}, {%4,%5,%6,%7}, {%8,%9}, {%0,%1,%2,%3};"
        : "+f"(c[0]), "+f"(c[1]), "+f"(c[2]), "+f"(c[3])
        : "r"(a[0]), "r"(a[1]), "r"(a[2]), "r"(a[3]), "r"(b[0]), "r"(b[1]));
}

// ---------------- 2-way mask split of the K weight half ---------------------
__global__ void split_wk(const float* __restrict__ w) {
    int i = blockIdx.x * 256 + threadIdx.x;     // 0 .. C*C-1
    float v = w[(size_t)C*C + i];               // k rows start at 512
    float a = tf32mask(v);
    g_wa[i] = a;
    g_wb[i] = tf32mask(v - a);                  // v - a exact
}

// ---------------- rope repack: (n,256) -> (256,n), both tables --------------
__global__ void repack_rope(const float* __restrict__ rc, const float* __restrict__ rs) {
    int idx = blockIdx.x * 256 + threadIdx.x;   // 0 .. 2*1048576-1
    if (idx < 1048576) {
        int j = idx >> 12, n = idx & 4095;
        g_cosT[idx] = rc[n*256 + j];
    } else {
        int i2 = idx - 1048576;
        int j = i2 >> 12, n = i2 & 4095;
        g_sinT[i2] = rs[n*256 + j];
    }
}

// ---------------- fold BN into dwconv ---------------------------------------
__global__ void fold_misc(const float* __restrict__ qdww, const float* __restrict__ qdwb,
                          const float* __restrict__ qbng, const float* __restrict__ qbnb,
                          const float* __restrict__ kdww, const float* __restrict__ kdwb,
                          const float* __restrict__ kbng, const float* __restrict__ kbnb) {
    int which = blockIdx.x;
    int c = threadIdx.x;
    const float* dww = which ? kdww : qdww;
    const float* dwb = which ? kdwb : qdwb;
    const float* bng = which ? kbng : qbng;
    const float* bnb = which ? kbnb : qbnb;
    float gs = bng[c] * (1.0f / sqrtf(1.0f + 1e-5f));
    #pragma unroll
    for (int i = 0; i < 9; i++)
        g_fw[which*C*9 + c*9 + i] = dww[c*9 + i] * gs;
    g_fb[which*C + c] = dwb[c] * gs + bnb[c];
}

// ---------------- Q GEMM: SIMT fp32 (exact numerics), 2 CTA/SM --------------
__global__ __launch_bounds__(256, 2) void gemm_q(const float* __restrict__ x,
                                                 const float* __restrict__ w,
                                                 const float* __restrict__ bias) {
    __shared__ __align__(16) float As[2][8][132];
    __shared__ __align__(16) float Bs[2][8][132];
    __shared__ __align__(16) float stage[128][33];

    const int tid = threadIdx.x;
    const int m0 = blockIdx.y * 128;
    const int o0 = blockIdx.x * 128;       // 0..384 (q half only)
    const int tr = tid >> 4;
    const int tc = tid & 15;

    const int lr = tid >> 1;
    const int lk = (tid & 1) * 4;

    const float* xp = x + (size_t)(m0 + lr) * 512 + lk;
    const float* wp = w + (size_t)(o0 + lr) * 512 + lk;

    {
        float4 xa = *(const float4*)xp;
        float4 wb = *(const float4*)wp;
        As[0][lk+0][lr] = xa.x; As[0][lk+1][lr] = xa.y;
        As[0][lk+2][lr] = xa.z; As[0][lk+3][lr] = xa.w;
        Bs[0][lk+0][lr] = wb.x; Bs[0][lk+1][lr] = wb.y;
        Bs[0][lk+2][lr] = wb.z; Bs[0][lk+3][lr] = wb.w;
    }
    __syncthreads();

    float acc[8][8];
    #pragma unroll
    for (int i = 0; i < 8; i++)
        #pragma unroll
        for (int j = 0; j < 8; j++) acc[i][j] = 0.f;

    int buf = 0;
    for (int k0 = 0; k0 < 512; k0 += 8) {
        float4 nxa, nwb;
        const bool more = (k0 + 8 < 512);
        if (more) {
            nxa = *(const float4*)(xp + k0 + 8);
            nwb = *(const float4*)(wp + k0 + 8);
        }
        #pragma unroll
        for (int kk = 0; kk < 8; kk++) {
            float a[8], b[8];
            *(float4*)&a[0] = *(const float4*)&As[buf][kk][tr*4];
            *(float4*)&a[4] = *(const float4*)&As[buf][kk][64 + tr*4];
            *(float4*)&b[0] = *(const float4*)&Bs[buf][kk][tc*4];
            *(float4*)&b[4] = *(const float4*)&Bs[buf][kk][64 + tc*4];
            #pragma unroll
            for (int i = 0; i < 8; i++)
                #pragma unroll
                for (int j = 0; j < 8; j++)
                    acc[i][j] = fmaf(a[i], b[j], acc[i][j]);
        }
        if (more) {
            int nb = buf ^ 1;
            As[nb][lk+0][lr] = nxa.x; As[nb][lk+1][lr] = nxa.y;
            As[nb][lk+2][lr] = nxa.z; As[nb][lk+3][lr] = nxa.w;
            Bs[nb][lk+0][lr] = nwb.x; Bs[nb][lk+1][lr] = nwb.y;
            Bs[nb][lk+2][lr] = nwb.z; Bs[nb][lk+3][lr] = nwb.w;
            __syncthreads();
            buf = nb;
        }
    }

    float bv[8];
    #pragma unroll
    for (int j = 0; j < 4; j++) {
        bv[j]   = bias[o0 + tc*4 + j];
        bv[j+4] = bias[o0 + 64 + tc*4 + j];
    }

    const int bimg = m0 >> 12;
    const int nbase = m0 & 4095;

    for (int ch = 0; ch < 4; ch++) {
        __syncthreads();
        if (ch < 2) {
            if ((tc >> 3) == ch) {
                int clbase = tc*4 - ch*32;
                #pragma unroll
                for (int i = 0; i < 4; i++)
                    #pragma unroll
                    for (int j = 0; j < 4; j++)
                        stage[tr*4 + i][clbase + j] = acc[i][j] + bv[j];
                #pragma unroll
                for (int i = 0; i < 4; i++)
                    #pragma unroll
                    for (int j = 0; j < 4; j++)
                        stage[64 + tr*4 + i][clbase + j] = acc[i+4][j] + bv[j];
            }
        } else {
            if ((tc >> 3) == (ch - 2)) {
                int clbase = tc*4 - (ch-2)*32;
                #pragma unroll
                for (int i = 0; i < 4; i++)
                    #pragma unroll
                    for (int j = 0; j < 4; j++)
                        stage[tr*4 + i][clbase + j] = acc[i][j+4] + bv[j+4];
                #pragma unroll
                for (int i = 0; i < 4; i++)
                    #pragma unroll
                    for (int j = 0; j < 4; j++)
                        stage[64 + tr*4 + i][clbase + j] = acc[i+4][j+4] + bv[j+4];
            }
        }
        __syncthreads();
        #pragma unroll
        for (int i = 0; i < 16; i++) {
            int lin = tid + i*256;
            int r  = lin & 127;
            int cl = lin >> 7;
            int o  = o0 + ch*32 + cl;
            int n = nbase + r;
            g_qn[((size_t)(bimg*C + o))*NPIX + n] = stage[r][cl];
        }
    }
}

// ---------------- K GEMM: tf32 MMA, 2-way split, chunked accumulators -------
// 512 threads, 16 warps (4m x 4n), warp tile 32x32 -> acc[2][4][4] (32 regs).
#define GT_P 17
#define GT_T (128*GT_P)

__global__ __launch_bounds__(512) void gemm_k(const float* __restrict__ x,
                                              const float* __restrict__ bias) {
    __shared__ __align__(16) float sm[4*GT_T];
    float* As0 = sm;
    float* As1 = sm + GT_T;
    float* Bs0 = sm + 2*GT_T;
    float* Bs1 = sm + 3*GT_T;
    float* stage = sm;

    const int tid = threadIdx.x;
    const int wid = tid >> 5;
    const int lane = tid & 31;
    const int warp_m = wid >> 2;      // 0..3 -> 32 rows
    const int warp_n = wid & 3;       // 0..3 -> 32 cols
    const int m0 = blockIdx.y * 128;
    const int o0 = blockIdx.x * 128;  // k-local 0..384
    const int bg = lane >> 2;
    const int tig = lane & 3;

    float acc[2][4][4], accT[2][4][4];
    #pragma unroll
    for (int mt = 0; mt < 2; mt++)
        #pragma unroll
        for (int nt = 0; nt < 4; nt++)
            #pragma unroll
            for (int r = 0; r < 4; r++) { acc[mt][nt][r] = 0.f; accT[mt][nt][r] = 0.f; }

    const int rowl = tid >> 2;        // 0..127
    const int ql = tid & 3;

    float4 av, bav, bbv;
    av  = *(const float4*)(x    + (size_t)(m0 + rowl)*512 + ql*4);
    bav = *(const float4*)(g_wa + (size_t)(o0 + rowl)*512 + ql*4);
    bbv = *(const float4*)(g_wb + (size_t)(o0 + rowl)*512 + ql*4);

    for (int ch = 0; ch < 32; ch++) {
        {
            float va[4] = {av.x, av.y, av.z, av.w};
            float wa[4] = {bav.x, bav.y, bav.z, bav.w};
            float wb[4] = {bbv.x, bbv.y, bbv.z, bbv.w};
            #pragma unroll
            for (int j = 0; j < 4; j++) {
                float a1 = tf32mask(va[j]);
                As0[rowl*GT_P + ql*4 + j] = a1;
                As1[rowl*GT_P + ql*4 + j] = tf32mask(va[j] - a1);
                Bs0[rowl*GT_P + ql*4 + j] = wa[j];
                Bs1[rowl*GT_P + ql*4 + j] = wb[j];
            }
        }
        __syncthreads();

        if (ch < 31) {
            int kc = (ch + 1) * 16;
            av  = *(const float4*)(x    + (size_t)(m0 + rowl)*512 + kc + ql*4);
            bav = *(const float4*)(g_wa + (size_t)(o0 + rowl)*512 + kc + ql*4);
            bbv = *(const float4*)(g_wb + (size_t)(o0 + rowl)*512 + kc + ql*4);
        }

        #pragma unroll
        for (int k8 = 0; k8 < 16; k8 += 8) {
            uint32_t Bf0[4][2], Bf1[4][2];
            #pragma unroll
            for (int nt = 0; nt < 4; nt++) {
                int brow = warp_n*32 + nt*8 + bg;
                int bq = tig + k8;
                Bf0[nt][0] = __float_as_uint(Bs0[brow*GT_P + bq]);
                Bf0[nt][1] = __float_as_uint(Bs0[brow*GT_P + bq + 4]);
                Bf1[nt][0] = __float_as_uint(Bs1[brow*GT_P + bq]);
                Bf1[nt][1] = __float_as_uint(Bs1[brow*GT_P + bq + 4]);
            }
            #pragma unroll
            for (int mt = 0; mt < 2; mt++) {
                int arow = warp_m*32 + mt*16 + bg;
                int aq = tig + k8;
                uint32_t Af0[4], Af1[4];
                Af0[0] = __float_as_uint(As0[arow*GT_P + aq]);
                Af0[1] = __float_as_uint(As0[(arow+8)*GT_P + aq]);
                Af0[2] = __float_as_uint(As0[arow*GT_P + aq + 4]);
                Af0[3] = __float_as_uint(As0[(arow+8)*GT_P + aq + 4]);
                Af1[0] = __float_as_uint(As1[arow*GT_P + aq]);
                Af1[1] = __float_as_uint(As1[(arow+8)*GT_P + aq]);
                Af1[2] = __float_as_uint(As1[arow*GT_P + aq + 4]);
                Af1[3] = __float_as_uint(As1[(arow+8)*GT_P + aq + 4]);
                #pragma unroll
                for (int nt = 0; nt < 4; nt++) {
                    mma8(acc[mt][nt], Af0, Bf0[nt]);
                    mma8(acc[mt][nt], Af0, Bf1[nt]);
                    mma8(acc[mt][nt], Af1, Bf0[nt]);
                    mma8(acc[mt][nt], Af1, Bf1[nt]);
                }
            }
        }
        if (ch == 15) {
            #pragma unroll
            for (int mt = 0; mt < 2; mt++)
                #pragma unroll
                for (int nt = 0; nt < 4; nt++)
                    #pragma unroll
                    for (int r = 0; r < 4; r++) {
                        accT[mt][nt][r] = acc[mt][nt][r];
                        acc[mt][nt][r] = 0.f;
                    }
        }
        __syncthreads();
    }

    const int bimg = m0 >> 12;
    const int nbase = m0 & 4095;
    for (int ch = 0; ch < 4; ch++) {
        if (warp_n == ch) {
            #pragma unroll
            for (int mt = 0; mt < 2; mt++) {
                int row = warp_m*32 + mt*16 + bg;
                #pragma unroll
                for (int nt = 0; nt < 4; nt++) {
                    int col = nt*8 + tig*2;
                    stage[row*33 + col]       = accT[mt][nt][0] + acc[mt][nt][0];
                    stage[row*33 + col + 1]   = accT[mt][nt][1] + acc[mt][nt][1];
                    stage[(row+8)*33 + col]   = accT[mt][nt][2] + acc[mt][nt][2];
                    stage[(row+8)*33 + col+1] = accT[mt][nt][3] + acc[mt][nt][3];
                }
            }
        }
        __syncthreads();
        #pragma unroll
        for (int i = 0; i < 8; i++) {
            int lin = tid + i*512;
            int m = lin & 127;
            int ol = lin >> 7;
            int o = o0 + ch*32 + ol;            // k-local channel
            float val = stage[m*33 + ol] + bias[512 + o];
            int n = nbase + m;
            g_kn[((size_t)(bimg*C + o))*NPIX + n] = val;
        }
        __syncthreads();
    }
}

// ---------------- spatial gate: dwconv(+folded BN)+relu, partial per block --
__global__ __launch_bounds__(512) void gate_accum(int which, const float* __restrict__ pww) {
    const float* src = which ? g_kn : g_qn;
    const float* fw = g_fw + which*C*9;
    const float* fb = g_fb + which*C;
    int b  = blockIdx.z;
    int cb = blockIdx.y;                // channel block 0..7
    int r0 = blockIdx.x * 8;
    int c0 = cb * 64;
    int tid = threadIdx.x;
    int r  = tid >> 6;
    int wx = tid & 63;
    __shared__ float tile[10][64];
    float acc = 0.f, comp = 0.f;
    for (int c = c0; c < c0 + 64; c++) {
        const float* plane = src + ((size_t)(b*C + c)) * NPIX;
        #pragma unroll
        for (int lin = tid; lin < 640; lin += 512) {
            int rr = (lin >> 6) + r0 - 1;
            int cc = lin & 63;
            tile[lin >> 6][cc] = (rr >= 0 && rr < 64) ? plane[rr*64 + cc] : 0.f;
        }
        __syncthreads();
        float conv = fb[c];
        #pragma unroll
        for (int kh = 0; kh < 3; kh++) {
            #pragma unroll
            for (int kw = 0; kw < 3; kw++) {
                int cc = wx + kw - 1;
                float v = (cc >= 0 && cc < 64) ? tile[r + kh][cc] : 0.f;
                conv = fmaf(v, fw[c*9 + kh*3 + kw], conv);
            }
        }
        float y = fmaxf(conv, 0.f);
        float p = y * pww[c];
        float yy = p - comp;
        float tt = acc + yy;
        comp = (tt - acc) - yy;
        acc = tt;
        __syncthreads();
    }
    g_gpart[((size_t)(which*8 + cb)*B + b)*NPIX + (r0 + r)*64 + wx] = acc;
}

// ---------------- gate finish: fixed-order partial sum + sigmoid ------------
__global__ void gate_finish() {
    int idx = blockIdx.x * 256 + threadIdx.x;   // 0 .. 2*B*NPIX-1
    int t = idx >> 15;                          // B*NPIX = 32768
    int rem = idx & 32767;
    float s = 0.f;
    #pragma unroll
    for (int cb = 0; cb < 8; cb++)
        s += g_gpart[((size_t)(t*8 + cb) << 15) + rem];
    g_gate[idx] = acc_sigmoid(s);
}

// ---------------- channel pool + SE gemm -----------------------------------
__global__ __launch_bounds__(256) void pool_kernel() {
    int t = blockIdx.z, b = blockIdx.y, c = blockIdx.x;
    const float* src  = t ? g_kn : g_qn;
    const float* gate = g_gate + t*B*NPIX + b*NPIX;
    const float* plane = src + ((size_t)(b*C + c)) * NPIX;
    float s = 0.f;
    for (int n = threadIdx.x; n < NPIX; n += 256) s = fmaf(plane[n], gate[n], s);
    __shared__ float red[8];
    for (int off = 16; off; off >>= 1) s += __shfl_down_sync(0xffffffffu, s, off);
    if ((threadIdx.x & 31) == 0) red[threadIdx.x >> 5] = s;
    __syncthreads();
    if (threadIdx.x < 8) {
        s = red[threadIdx.x];
        for (int off = 4; off; off >>= 1) s += __shfl_down_sync(0xffu, s, off);
        if (threadIdx.x == 0) g_pool[t*B*C + b*C + c] = s * (1.f / NPIX);
    }
}

__global__ __launch_bounds__(512) void chgemm(const float* __restrict__ qw,
                                              const float* __restrict__ kw) {
    int t = blockIdx.y, b = blockIdx.x;
    const float* wm = t ? kw : qw;
    __shared__ float ps[512];
    ps[threadIdx.x] = g_pool[t*B*C + b*C + threadIdx.x];
    __syncthreads();
    int o = threadIdx.x;
    float acc = 0.f, comp = 0.f;
    for (int c2 = 0; c2 < 512; c2++) {
        float p = ps[c2] * wm[o*512 + c2];
        float yy = p - comp;
        float tt = acc + yy;
        comp = (tt - acc) - yy;
        acc = tt;
    }
    g_cs[t*B*C + b*C + o] = acc_sigmoid(acc);
}

// ---------------- kv state + k_mean per (b, head) --------------------------
__global__ __launch_bounds__(256) void kv_kernel(const float* __restrict__ x) {
    int h = blockIdx.x, b = blockIdx.y;
    int c0 = h * HD, jg0 = h * 16;
    __shared__ float kt[32][132];
    __shared__ __align__(16) float vt[128][36];
    int tid = threadIdx.x;
    int d = tid >> 3, g = tid & 7;
    const float* gate = g_gate + B*NPIX + b*NPIX;   // k side
    float4 acc = make_float4(0.f, 0.f, 0.f, 0.f);
    double kmd = 0.0;
    for (int t0 = 0; t0 < NPIX; t0 += 128) {
        #pragma unroll
        for (int i = 0; i < 16; i++) {
            int lin = tid + i*256;
            int dd = lin >> 7, col = lin & 127;
            int n = t0 + col;
            float v = g_kn[((size_t)(b*C + c0 + dd))*NPIX + n]
                      * gate[n] * g_cs[B*C + b*C + c0 + dd];
            kt[dd][col] = elu1(v);
        }
        #pragma unroll
        for (int i = 0; i < 16; i++) {
            int lin = tid + i*256;
            int col = lin >> 5, ee = lin & 31;
            vt[col][ee] = x[((size_t)(b*NPIX + t0 + col))*C + c0 + ee];
        }
        __syncthreads();
        #pragma unroll
        for (int i = 0; i < 8; i++) {
            int lin = tid + i*256;
            int j = lin >> 7, col = lin & 127;
            float cv = g_cosT[(jg0 + j)*NPIX + t0 + col];
            float sv = g_sinT[(jg0 + j)*NPIX + t0 + col];
            float xr = kt[2*j][col], xi = kt[2*j+1][col];
            kt[2*j][col]   = cv*xr - sv*xi;
            kt[2*j+1][col] = sv*xr + cv*xi;
        }
        __syncthreads();
        float kmf = 0.f, kmc = 0.f;
        #pragma unroll 4
        for (int col = 0; col < 128; col++) {
            float kd = kt[d][col];
            float4 v4 = *(const float4*)&vt[col][g*4];
            acc.x = fmaf(kd, v4.x, acc.x);
            acc.y = fmaf(kd, v4.y, acc.y);
            acc.z = fmaf(kd, v4.z, acc.z);
            acc.w = fmaf(kd, v4.w, acc.w);
            float yy = kd - kmc;
            float tt = kmf + yy;
            kmc = (tt - kmf) - yy;
            kmf = tt;
        }
        kmd += (double)kmf;
        __syncthreads();
    }
    float* kvp = g_kv + ((size_t)((b*HEADS + h)*HD + d))*HD + g*4;
    kvp[0] = acc.x * (1.f / NPIX);
    kvp[1] = acc.y * (1.f / NPIX);
    kvp[2] = acc.z * (1.f / NPIX);
    kvp[3] = acc.w * (1.f / NPIX);
    if (g == 0) g_km[(b*HEADS + h)*HD + d] = (float)(kmd * (1.0 / NPIX));
}

// ---------------- output: q_rope @ kv * z + lepe ---------------------------
__global__ __launch_bounds__(256) void out_kernel(const float* __restrict__ x,
        const float* __restrict__ lw, const float* __restrict__ lb,
        float* __restrict__ out) {
    int n0 = blockIdx.x * 128;
    int h = blockIdx.y, b = blockIdx.z;
    int c0 = h * HD, jg0 = h * 16;
    __shared__ float qt[32][129];
    __shared__ float kvs[32][32];
    __shared__ float kms[32];
    __shared__ float xs[4][64][32];
    int tid = threadIdx.x;
    int hh0 = n0 >> 6;
    const float* gate = g_gate + b*NPIX;  // q side
    #pragma unroll
    for (int i = 0; i < 16; i++) {
        int lin = tid + i*256;
        int dd = lin >> 7, col = lin & 127;
        int n = n0 + col;
        float v = g_qn[((size_t)(b*C + c0 + dd))*NPIX + n]
                  * gate[n] * g_cs[b*C + c0 + dd];
        qt[dd][col] = elu1(v);
    }
    #pragma unroll
    for (int i = 0; i < 32; i++) {
        int lin = tid + i*256;
        int cch  = lin & 31;
        int ccol = (lin >> 5) & 63;
        int ri   = lin >> 11;
        int rr = hh0 - 1 + ri;
        xs[ri][ccol][cch] = (rr >= 0 && rr < 64)
            ? x[((size_t)(b*NPIX + rr*64 + ccol))*C + c0 + cch] : 0.f;
    }
    #pragma unroll
    for (int i = 0; i < 4; i++) {
        int lin = tid + i*256;
        kvs[lin >> 5][lin & 31] = g_kv[((size_t)(b*HEADS + h))*HD*HD + lin];
    }
    if (tid < 32) kms[tid] = g_km[(b*HEADS + h)*HD + tid];
    __syncthreads();
    #pragma unroll
    for (int i = 0; i < 8; i++) {
        int lin = tid + i*256;
        int j = lin >> 7, col = lin & 127;
        float cv = g_cosT[(jg0 + j)*NPIX + n0 + col];
        float sv = g_sinT[(jg0 + j)*NPIX + n0 + col];
        float xr = qt[2*j][col], xi = qt[2*j+1][col];
        qt[2*j][col]   = cv*xr - sv*xi;
        qt[2*j+1][col] = sv*xr + cv*xi;
    }
    __syncthreads();

    int e = tid & 31;
    int grp = tid >> 5;
    int c = c0 + e;
    float wloc[9];
    #pragma unroll
    for (int i2 = 0; i2 < 9; i2++) wloc[i2] = lw[c*9 + i2];
    float lbv = lb[c];

    for (int ci = 0; ci < 16; ci++) {
        int col = grp*16 + ci;
        int n = n0 + col;
        float a1 = 0.f;
        float s2 = 0.f, cmp = 0.f, pe = 0.f;
        #pragma unroll
        for (int dd = 0; dd < 32; dd++) {
            float qv = qt[dd][col];
            a1 = fmaf(qv, kvs[dd][e], a1);
            float kmv = kms[dd];
            float p = qv * kmv;
            pe += fmaf(qv, kmv, -p);
            float yy = p - cmp;
            float tt = s2 + yy;
            cmp = (tt - s2) - yy;
            s2 = tt;
        }
        float a2 = s2 + pe;
        float z = 1.f / (a2 + 1e-6f);
        float att = a1 * z;
        int hh = n >> 6, ww2 = n & 63;
        int rbase = hh - hh0;
        float lep = lbv;
        #pragma unroll
        for (int kh = 0; kh < 3; kh++) {
            #pragma unroll
            for (int kw = 0; kw < 3; kw++) {
                int cc2 = ww2 + kw - 1;
                if (cc2 < 0 || cc2 >= 64) continue;
                lep = fmaf(wloc[kh*3 + kw], xs[rbase + kh][cc2][e], lep);
            }
        }
        out[((size_t)(b*NPIX + n))*C + c] = att + lep;
    }
}

// ---------------- launch ----------------------------------------------------
extern "C" void kernel_launch(void* const* d_in, const int* in_sizes, int n_in,
                              void* d_out, int out_size) {
    const float* x        = (const float*)d_in[0];
    const float* qk_w     = (const float*)d_in[1];
    const float* qk_b     = (const float*)d_in[2];
    const float* qsp_dw_w = (const float*)d_in[3];
    const float* qsp_dw_b = (const float*)d_in[4];
    const float* qsp_bn_g = (const float*)d_in[5];
    const float* qsp_bn_b = (const float*)d_in[6];
    const float* qsp_pw_w = (const float*)d_in[7];
    const float* qch_w    = (const float*)d_in[8];
    const float* ksp_dw_w = (const float*)d_in[9];
    const float* ksp_dw_b = (const float*)d_in[10];
    const float* ksp_bn_g = (const float*)d_in[11];
    const float* ksp_bn_b = (const float*)d_in[12];
    const float* ksp_pw_w = (const float*)d_in[13];
    const float* kch_w    = (const float*)d_in[14];
    const float* lepe_w   = (const float*)d_in[15];
    const float* lepe_b   = (const float*)d_in[16];
    const float* rope_cos = (const float*)d_in[17];
    const float* rope_sin = (const float*)d_in[18];
    float* out = (float*)d_out;

    split_wk<<<1024, 256>>>(qk_w);                                     // 1
    repack_rope<<<8192, 256>>>(rope_cos, rope_sin);                    // 2
    fold_misc<<<2, 512>>>(qsp_dw_w, qsp_dw_b, qsp_bn_g, qsp_bn_b,
                          ksp_dw_w, ksp_dw_b, ksp_bn_g, ksp_bn_b);     // 3
    gemm_q<<<dim3(4, 256), 256>>>(x, qk_w, qk_b);                      // 4 (profile target)
    gemm_k<<<dim3(4, 256), 512>>>(x, qk_b);                            // 5
    gate_accum<<<dim3(8, 8, B), 512>>>(0, qsp_pw_w);                   // 6
    gate_accum<<<dim3(8, 8, B), 512>>>(1, ksp_pw_w);                   // 7
    gate_finish<<<(2*B*NPIX)/256, 256>>>();                            // 8
    pool_kernel<<<dim3(C, B, 2), 256>>>();                             // 9
    chgemm<<<dim3(B, 2), 512>>>(qch_w, kch_w);                         // 10
    kv_kernel<<<dim3(HEADS, B), 256>>>(x);                             // 11
    out_kernel<<<dim3(32, HEADS, B), 256>>>(x, lepe_w, lepe_b, out);   // 12
}

// round 16
// speedup vs baseline: 1.0798x; 1.0798x over previous
#include <cuda_runtime.h>
#include <math.h>
#include <cstdint>

#define B 8
#define NPIX 4096
#define C 512
#define HEADS 16
#define HD 32

// ---------------- scratch (device globals; no runtime allocation) ----------
__device__ float g_qn[B*C*NPIX];        // q projection, (b,c,n) layout
__device__ float g_kn[B*C*NPIX];        // k projection, (b,c,n) layout
__device__ float g_gate[2*B*NPIX];      // spatial gate (sigmoid), q then k
__device__ float g_gpart[16*B*NPIX];    // gate partials: (which*8+cb, b, pix)
__device__ float g_pool[2*B*C];
__device__ float g_cs[2*B*C];           // channel gate (q then k)
__device__ float g_cosT[256*NPIX];      // rope cos, (j, n) layout
__device__ float g_sinT[256*NPIX];
__device__ float g_kv[B*HEADS*HD*HD];
__device__ float g_km[B*HEADS*HD];
__device__ float g_fw[2*C*9];           // folded dwconv weights (w * bn_scale)
__device__ float g_fb[2*C];             // folded bias
// tf32 2-way split of the K half of qk_w (rows 512..1023)
__device__ __align__(16) float g_wa[C*C];
__device__ __align__(16) float g_wb[C*C];

__device__ __forceinline__ float acc_sigmoid(float x) {
    return 1.0f / (1.0f + expf(-x));
}
__device__ __forceinline__ float elu1(float x) {
    return x > 0.0f ? x + 1.0f : expf(x);
}
__device__ __forceinline__ float tf32mask(float v) {
    return __uint_as_float(__float_as_uint(v) & 0xFFFFE000u);
}
__device__ __forceinline__ void mma8(float* c, const uint32_t* a, const uint32_t* b) {
    asm volatile("mma.sync.aligned.m16n8k8.row.col.f32.tf32.tf32.f32 "
        "{%0,%1,%2,%3}, {%4,%5,%6,%7}, {%8,%9}, {%0,%1,%2,%3};"
        : "+f"(c[0]), "+f"(c[1]), "+f"(c[2]), "+f"(c[3])
        : "r"(a[0]), "r"(a[1]), "r"(a[2]), "r"(a[3]), "r"(b[0]), "r"(b[1]));
}

// ---------------- 2-way mask split of the K weight half ---------------------
__global__ void split_wk(const float* __restrict__ w) {
    int i = blockIdx.x * 256 + threadIdx.x;     // 0 .. C*C-1
    float v = w[(size_t)C*C + i];               // k rows start at 512
    float a = tf32mask(v);
    g_wa[i] = a;
    g_wb[i] = tf32mask(v - a);                  // v - a exact
}

// ---------------- rope repack: (n,256) -> (256,n), both tables --------------
__global__ void repack_rope(const float* __restrict__ rc, const float* __restrict__ rs) {
    int idx = blockIdx.x * 256 + threadIdx.x;   // 0 .. 2*1048576-1
    if (idx < 1048576) {
        int j = idx >> 12, n = idx & 4095;
        g_cosT[idx] = rc[n*256 + j];
    } else {
        int i2 = idx - 1048576;
        int j = i2 >> 12, n = i2 & 4095;
        g_sinT[i2] = rs[n*256 + j];
    }
}

// ---------------- fold BN into dwconv ---------------------------------------
__global__ void fold_misc(const float* __restrict__ qdww, const float* __restrict__ qdwb,
                          const float* __restrict__ qbng, const float* __restrict__ qbnb,
                          const float* __restrict__ kdww, const float* __restrict__ kdwb,
                          const float* __restrict__ kbng, const float* __restrict__ kbnb) {
    int which = blockIdx.x;
    int c = threadIdx.x;
    const float* dww = which ? kdww : qdww;
    const float* dwb = which ? kdwb : qdwb;
    const float* bng = which ? kbng : qbng;
    const float* bnb = which ? kbnb : qbnb;
    float gs = bng[c] * (1.0f / sqrtf(1.0f + 1e-5f));
    #pragma unroll
    for (int i = 0; i < 9; i++)
        g_fw[which*C*9 + c*9 + i] = dww[c*9 + i] * gs;
    g_fb[which*C + c] = dwb[c] * gs + bnb[c];
}

// ---------------- K GEMM: tf32 MMA, 2-way split, chunked accumulators -------
// 512 threads, 16 warps (4m x 4n), warp tile 32x32 -> acc[2][4][4] (32 regs).
// Pitch 36 floats: conflict-free fragment loads + aligned STS.128 stores.
#define GT_P 36
#define GT_T (128*GT_P)
#define GT_SMEM (4*GT_T*4)   // 73728 bytes dynamic

__global__ __launch_bounds__(512) void gemm_k(const float* __restrict__ x,
                                              const float* __restrict__ bias) {
    extern __shared__ __align__(16) float sm[];
    float* As0 = sm;
    float* As1 = sm + GT_T;
    float* Bs0 = sm + 2*GT_T;
    float* Bs1 = sm + 3*GT_T;
    float* stage = sm;

    const int tid = threadIdx.x;
    const int wid = tid >> 5;
    const int lane = tid & 31;
    const int warp_m = wid >> 2;      // 0..3 -> 32 rows
    const int warp_n = wid & 3;       // 0..3 -> 32 cols
    const int m0 = blockIdx.y * 128;
    const int o0 = blockIdx.x * 128;  // k-local 0..384
    const int bg = lane >> 2;
    const int tig = lane & 3;

    float acc[2][4][4], accT[2][4][4];
    #pragma unroll
    for (int mt = 0; mt < 2; mt++)
        #pragma unroll
        for (int nt = 0; nt < 4; nt++)
            #pragma unroll
            for (int r = 0; r < 4; r++) { acc[mt][nt][r] = 0.f; accT[mt][nt][r] = 0.f; }

    const int rowl = tid >> 2;        // 0..127
    const int ql = tid & 3;

    float4 av, bav, bbv;
    av  = *(const float4*)(x    + (size_t)(m0 + rowl)*512 + ql*4);
    bav = *(const float4*)(g_wa + (size_t)(o0 + rowl)*512 + ql*4);
    bbv = *(const float4*)(g_wb + (size_t)(o0 + rowl)*512 + ql*4);

    for (int ch = 0; ch < 32; ch++) {
        {
            float va[4] = {av.x, av.y, av.z, av.w};
            float4 s0, s1;
            float* p0 = (float*)&s0;
            float* p1 = (float*)&s1;
            #pragma unroll
            for (int j = 0; j < 4; j++) {
                float a1 = tf32mask(va[j]);
                p0[j] = a1;
                p1[j] = tf32mask(va[j] - a1);
            }
            *(float4*)(As0 + rowl*GT_P + ql*4) = s0;
            *(float4*)(As1 + rowl*GT_P + ql*4) = s1;
            *(float4*)(Bs0 + rowl*GT_P + ql*4) = bav;
            *(float4*)(Bs1 + rowl*GT_P + ql*4) = bbv;
        }
        __syncthreads();

        if (ch < 31) {
            int kc = (ch + 1) * 16;
            av  = *(const float4*)(x    + (size_t)(m0 + rowl)*512 + kc + ql*4);
            bav = *(const float4*)(g_wa + (size_t)(o0 + rowl)*512 + kc + ql*4);
            bbv = *(const float4*)(g_wb + (size_t)(o0 + rowl)*512 + kc + ql*4);
        }

        #pragma unroll
        for (int k8 = 0; k8 < 16; k8 += 8) {
            uint32_t Bf0[4][2], Bf1[4][2];
            #pragma unroll
            for (int nt = 0; nt < 4; nt++) {
                int brow = warp_n*32 + nt*8 + bg;
                int bq = tig + k8;
                Bf0[nt][0] = __float_as_uint(Bs0[brow*GT_P + bq]);
                Bf0[nt][1] = __float_as_uint(Bs0[brow*GT_P + bq + 4]);
                Bf1[nt][0] = __float_as_uint(Bs1[brow*GT_P + bq]);
                Bf1[nt][1] = __float_as_uint(Bs1[brow*GT_P + bq + 4]);
            }
            #pragma unroll
            for (int mt = 0; mt < 2; mt++) {
                int arow = warp_m*32 + mt*16 + bg;
                int aq = tig + k8;
                uint32_t Af0[4], Af1[4];
                Af0[0] = __float_as_uint(As0[arow*GT_P + aq]);
                Af0[1] = __float_as_uint(As0[(arow+8)*GT_P + aq]);
                Af0[2] = __float_as_uint(As0[arow*GT_P + aq + 4]);
                Af0[3] = __float_as_uint(As0[(arow+8)*GT_P + aq + 4]);
                Af1[0] = __float_as_uint(As1[arow*GT_P + aq]);
                Af1[1] = __float_as_uint(As1[(arow+8)*GT_P + aq]);
                Af1[2] = __float_as_uint(As1[arow*GT_P + aq + 4]);
                Af1[3] = __float_as_uint(As1[(arow+8)*GT_P + aq + 4]);
                #pragma unroll
                for (int nt = 0; nt < 4; nt++) {
                    mma8(acc[mt][nt], Af0, Bf0[nt]);
                    mma8(acc[mt][nt], Af0, Bf1[nt]);
                    mma8(acc[mt][nt], Af1, Bf0[nt]);
                    mma8(acc[mt][nt], Af1, Bf1[nt]);
                }
            }
        }
        if (ch == 15) {
            #pragma unroll
            for (int mt = 0; mt < 2; mt++)
                #pragma unroll
                for (int nt = 0; nt < 4; nt++)
                    #pragma unroll
                    for (int r = 0; r < 4; r++) {
                        accT[mt][nt][r] = acc[mt][nt][r];
                        acc[mt][nt][r] = 0.f;
                    }
        }
        __syncthreads();
    }

    const int bimg = m0 >> 12;
    const int nbase = m0 & 4095;
    for (int ch = 0; ch < 4; ch++) {
        if (warp_n == ch) {
            #pragma unroll
            for (int mt = 0; mt < 2; mt++) {
                int row = warp_m*32 + mt*16 + bg;
                #pragma unroll
                for (int nt = 0; nt < 4; nt++) {
                    int col = nt*8 + tig*2;
                    stage[row*33 + col]       = accT[mt][nt][0] + acc[mt][nt][0];
                    stage[row*33 + col + 1]   = accT[mt][nt][1] + acc[mt][nt][1];
                    stage[(row+8)*33 + col]   = accT[mt][nt][2] + acc[mt][nt][2];
                    stage[(row+8)*33 + col+1] = accT[mt][nt][3] + acc[mt][nt][3];
                }
            }
        }
        __syncthreads();
        #pragma unroll
        for (int i = 0; i < 8; i++) {
            int lin = tid + i*512;
            int m = lin & 127;
            int ol = lin >> 7;
            int o = o0 + ch*32 + ol;            // k-local channel
            float val = stage[m*33 + ol] + bias[512 + o];
            int n = nbase + m;
            g_kn[((size_t)(bimg*C + o))*NPIX + n] = val;
        }
        __syncthreads();
    }
}

// ---------------- Q GEMM: SIMT fp32 (exact numerics), 2 CTA/SM --------------
__global__ __launch_bounds__(256, 2) void gemm_q(const float* __restrict__ x,
                                                 const float* __restrict__ w,
                                                 const float* __restrict__ bias) {
    __shared__ __align__(16) float As[2][8][132];
    __shared__ __align__(16) float Bs[2][8][132];
    __shared__ __align__(16) float stage[128][33];

    const int tid = threadIdx.x;
    const int m0 = blockIdx.y * 128;
    const int o0 = blockIdx.x * 128;       // 0..384 (q half only)
    const int tr = tid >> 4;
    const int tc = tid & 15;

    const int lr = tid >> 1;
    const int lk = (tid & 1) * 4;

    const float* xp = x + (size_t)(m0 + lr) * 512 + lk;
    const float* wp = w + (size_t)(o0 + lr) * 512 + lk;

    {
        float4 xa = *(const float4*)xp;
        float4 wb = *(const float4*)wp;
        As[0][lk+0][lr] = xa.x; As[0][lk+1][lr] = xa.y;
        As[0][lk+2][lr] = xa.z; As[0][lk+3][lr] = xa.w;
        Bs[0][lk+0][lr] = wb.x; Bs[0][lk+1][lr] = wb.y;
        Bs[0][lk+2][lr] = wb.z; Bs[0][lk+3][lr] = wb.w;
    }
    __syncthreads();

    float acc[8][8];
    #pragma unroll
    for (int i = 0; i < 8; i++)
        #pragma unroll
        for (int j = 0; j < 8; j++) acc[i][j] = 0.f;

    int buf = 0;
    for (int k0 = 0; k0 < 512; k0 += 8) {
        float4 nxa, nwb;
        const bool more = (k0 + 8 < 512);
        if (more) {
            nxa = *(const float4*)(xp + k0 + 8);
            nwb = *(const float4*)(wp + k0 + 8);
        }
        #pragma unroll
        for (int kk = 0; kk < 8; kk++) {
            float a[8], b[8];
            *(float4*)&a[0] = *(const float4*)&As[buf][kk][tr*4];
            *(float4*)&a[4] = *(const float4*)&As[buf][kk][64 + tr*4];
            *(float4*)&b[0] = *(const float4*)&Bs[buf][kk][tc*4];
            *(float4*)&b[4] = *(const float4*)&Bs[buf][kk][64 + tc*4];
            #pragma unroll
            for (int i = 0; i < 8; i++)
                #pragma unroll
                for (int j = 0; j < 8; j++)
                    acc[i][j] = fmaf(a[i], b[j], acc[i][j]);
        }
        if (more) {
            int nb = buf ^ 1;
            As[nb][lk+0][lr] = nxa.x; As[nb][lk+1][lr] = nxa.y;
            As[nb][lk+2][lr] = nxa.z; As[nb][lk+3][lr] = nxa.w;
            Bs[nb][lk+0][lr] = nwb.x; Bs[nb][lk+1][lr] = nwb.y;
            Bs[nb][lk+2][lr] = nwb.z; Bs[nb][lk+3][lr] = nwb.w;
            __syncthreads();
            buf = nb;
        }
    }

    float bv[8];
    #pragma unroll
    for (int j = 0; j < 4; j++) {
        bv[j]   = bias[o0 + tc*4 + j];
        bv[j+4] = bias[o0 + 64 + tc*4 + j];
    }

    const int bimg = m0 >> 12;
    const int nbase = m0 & 4095;

    for (int ch = 0; ch < 4; ch++) {
        __syncthreads();
        if (ch < 2) {
            if ((tc >> 3) == ch) {
                int clbase = tc*4 - ch*32;
                #pragma unroll
                for (int i = 0; i < 4; i++)
                    #pragma unroll
                    for (int j = 0; j < 4; j++)
                        stage[tr*4 + i][clbase + j] = acc[i][j] + bv[j];
                #pragma unroll
                for (int i = 0; i < 4; i++)
                    #pragma unroll
                    for (int j = 0; j < 4; j++)
                        stage[64 + tr*4 + i][clbase + j] = acc[i+4][j] + bv[j];
            }
        } else {
            if ((tc >> 3) == (ch - 2)) {
                int clbase = tc*4 - (ch-2)*32;
                #pragma unroll
                for (int i = 0; i < 4; i++)
                    #pragma unroll
                    for (int j = 0; j < 4; j++)
                        stage[tr*4 + i][clbase + j] = acc[i][j+4] + bv[j+4];
                #pragma unroll
                for (int i = 0; i < 4; i++)
                    #pragma unroll
                    for (int j = 0; j < 4; j++)
                        stage[64 + tr*4 + i][clbase + j] = acc[i+4][j+4] + bv[j+4];
            }
        }
        __syncthreads();
        #pragma unroll
        for (int i = 0; i < 16; i++) {
            int lin = tid + i*256;
            int r  = lin & 127;
            int cl = lin >> 7;
            int o  = o0 + ch*32 + cl;
            int n = nbase + r;
            g_qn[((size_t)(bimg*C + o))*NPIX + n] = stage[r][cl];
        }
    }
}

// ---------------- spatial gate: dwconv(+folded BN)+relu, partial per block --
__global__ __launch_bounds__(512) void gate_accum(int which, const float* __restrict__ pww) {
    const float* src = which ? g_kn : g_qn;
    const float* fw = g_fw + which*C*9;
    const float* fb = g_fb + which*C;
    int b  = blockIdx.z;
    int cb = blockIdx.y;                // channel block 0..7
    int r0 = blockIdx.x * 8;
    int c0 = cb * 64;
    int tid = threadIdx.x;
    int r  = tid >> 6;
    int wx = tid & 63;
    __shared__ float tile[10][64];
    float acc = 0.f, comp = 0.f;
    for (int c = c0; c < c0 + 64; c++) {
        const float* plane = src + ((size_t)(b*C + c)) * NPIX;
        #pragma unroll
        for (int lin = tid; lin < 640; lin += 512) {
            int rr = (lin >> 6) + r0 - 1;
            int cc = lin & 63;
            tile[lin >> 6][cc] = (rr >= 0 && rr < 64) ? plane[rr*64 + cc] : 0.f;
        }
        __syncthreads();
        float conv = fb[c];
        #pragma unroll
        for (int kh = 0; kh < 3; kh++) {
            #pragma unroll
            for (int kw = 0; kw < 3; kw++) {
                int cc = wx + kw - 1;
                float v = (cc >= 0 && cc < 64) ? tile[r + kh][cc] : 0.f;
                conv = fmaf(v, fw[c*9 + kh*3 + kw], conv);
            }
        }
        float y = fmaxf(conv, 0.f);
        float p = y * pww[c];
        float yy = p - comp;
        float tt = acc + yy;
        comp = (tt - acc) - yy;
        acc = tt;
        __syncthreads();
    }
    g_gpart[((size_t)(which*8 + cb)*B + b)*NPIX + (r0 + r)*64 + wx] = acc;
}

// ---------------- gate finish: fixed-order partial sum + sigmoid ------------
__global__ void gate_finish() {
    int idx = blockIdx.x * 256 + threadIdx.x;   // 0 .. 2*B*NPIX-1
    int t = idx >> 15;                          // B*NPIX = 32768
    int rem = idx & 32767;
    float s = 0.f;
    #pragma unroll
    for (int cb = 0; cb < 8; cb++)
        s += g_gpart[((size_t)(t*8 + cb) << 15) + rem];
    g_gate[idx] = acc_sigmoid(s);
}

// ---------------- channel pool + SE gemm -----------------------------------
__global__ __launch_bounds__(256) void pool_kernel() {
    int t = blockIdx.z, b = blockIdx.y, c = blockIdx.x;
    const float* src  = t ? g_kn : g_qn;
    const float* gate = g_gate + t*B*NPIX + b*NPIX;
    const float* plane = src + ((size_t)(b*C + c)) * NPIX;
    float s = 0.f;
    for (int n = threadIdx.x; n < NPIX; n += 256) s = fmaf(plane[n], gate[n], s);
    __shared__ float red[8];
    for (int off = 16; off; off >>= 1) s += __shfl_down_sync(0xffffffffu, s, off);
    if ((threadIdx.x & 31) == 0) red[threadIdx.x >> 5] = s;
    __syncthreads();
    if (threadIdx.x < 8) {
        s = red[threadIdx.x];
        for (int off = 4; off; off >>= 1) s += __shfl_down_sync(0xffu, s, off);
        if (threadIdx.x == 0) g_pool[t*B*C + b*C + c] = s * (1.f / NPIX);
    }
}

__global__ __launch_bounds__(512) void chgemm(const float* __restrict__ qw,
                                              const float* __restrict__ kw) {
    int t = blockIdx.y, b = blockIdx.x;
    const float* wm = t ? kw : qw;
    __shared__ float ps[512];
    ps[threadIdx.x] = g_pool[t*B*C + b*C + threadIdx.x];
    __syncthreads();
    int o = threadIdx.x;
    float acc = 0.f, comp = 0.f;
    for (int c2 = 0; c2 < 512; c2++) {
        float p = ps[c2] * wm[o*512 + c2];
        float yy = p - comp;
        float tt = acc + yy;
        comp = (tt - acc) - yy;
        acc = tt;
    }
    g_cs[t*B*C + b*C + o] = acc_sigmoid(acc);
}

// ---------------- kv state + k_mean per (b, head) --------------------------
__global__ __launch_bounds__(256) void kv_kernel(const float* __restrict__ x) {
    int h = blockIdx.x, b = blockIdx.y;
    int c0 = h * HD, jg0 = h * 16;
    __shared__ float kt[32][132];
    __shared__ __align__(16) float vt[128][36];
    int tid = threadIdx.x;
    int d = tid >> 3, g = tid & 7;
    const float* gate = g_gate + B*NPIX + b*NPIX;   // k side
    float4 acc = make_float4(0.f, 0.f, 0.f, 0.f);
    double kmd = 0.0;
    for (int t0 = 0; t0 < NPIX; t0 += 128) {
        #pragma unroll
        for (int i = 0; i < 16; i++) {
            int lin = tid + i*256;
            int dd = lin >> 7, col = lin & 127;
            int n = t0 + col;
            float v = g_kn[((size_t)(b*C + c0 + dd))*NPIX + n]
                      * gate[n] * g_cs[B*C + b*C + c0 + dd];
            kt[dd][col] = elu1(v);
        }
        #pragma unroll
        for (int i = 0; i < 16; i++) {
            int lin = tid + i*256;
            int col = lin >> 5, ee = lin & 31;
            vt[col][ee] = x[((size_t)(b*NPIX + t0 + col))*C + c0 + ee];
        }
        __syncthreads();
        #pragma unroll
        for (int i = 0; i < 8; i++) {
            int lin = tid + i*256;
            int j = lin >> 7, col = lin & 127;
            float cv = g_cosT[(jg0 + j)*NPIX + t0 + col];
            float sv = g_sinT[(jg0 + j)*NPIX + t0 + col];
            float xr = kt[2*j][col], xi = kt[2*j+1][col];
            kt[2*j][col]   = cv*xr - sv*xi;
            kt[2*j+1][col] = sv*xr + cv*xi;
        }
        __syncthreads();
        float kmf = 0.f, kmc = 0.f;
        #pragma unroll 4
        for (int col = 0; col < 128; col++) {
            float kd = kt[d][col];
            float4 v4 = *(const float4*)&vt[col][g*4];
            acc.x = fmaf(kd, v4.x, acc.x);
            acc.y = fmaf(kd, v4.y, acc.y);
            acc.z = fmaf(kd, v4.z, acc.z);
            acc.w = fmaf(kd, v4.w, acc.w);
            float yy = kd - kmc;
            float tt = kmf + yy;
            kmc = (tt - kmf) - yy;
            kmf = tt;
        }
        kmd += (double)kmf;
        __syncthreads();
    }
    float* kvp = g_kv + ((size_t)((b*HEADS + h)*HD + d))*HD + g*4;
    kvp[0] = acc.x * (1.f / NPIX);
    kvp[1] = acc.y * (1.f / NPIX);
    kvp[2] = acc.z * (1.f / NPIX);
    kvp[3] = acc.w * (1.f / NPIX);
    if (g == 0) g_km[(b*HEADS + h)*HD + d] = (float)(kmd * (1.0 / NPIX));
}

// ---------------- output: q_rope @ kv * z + lepe ---------------------------
__global__ __launch_bounds__(256) void out_kernel(const float* __restrict__ x,
        const float* __restrict__ lw, const float* __restrict__ lb,
        float* __restrict__ out) {
    int n0 = blockIdx.x * 128;
    int h = blockIdx.y, b = blockIdx.z;
    int c0 = h * HD, jg0 = h * 16;
    __shared__ float qt[32][129];
    __shared__ float kvs[32][32];
    __shared__ float kms[32];
    __shared__ float xs[4][64][32];
    int tid = threadIdx.x;
    int hh0 = n0 >> 6;
    const float* gate = g_gate + b*NPIX;  // q side
    #pragma unroll
    for (int i = 0; i < 16; i++) {
        int lin = tid + i*256;
        int dd = lin >> 7, col = lin & 127;
        int n = n0 + col;
        float v = g_qn[((size_t)(b*C + c0 + dd))*NPIX + n]
                  * gate[n] * g_cs[b*C + c0 + dd];
        qt[dd][col] = elu1(v);
    }
    #pragma unroll
    for (int i = 0; i < 32; i++) {
        int lin = tid + i*256;
        int cch  = lin & 31;
        int ccol = (lin >> 5) & 63;
        int ri   = lin >> 11;
        int rr = hh0 - 1 + ri;
        xs[ri][ccol][cch] = (rr >= 0 && rr < 64)
            ? x[((size_t)(b*NPIX + rr*64 + ccol))*C + c0 + cch] : 0.f;
    }
    #pragma unroll
    for (int i = 0; i < 4; i++) {
        int lin = tid + i*256;
        kvs[lin >> 5][lin & 31] = g_kv[((size_t)(b*HEADS + h))*HD*HD + lin];
    }
    if (tid < 32) kms[tid] = g_km[(b*HEADS + h)*HD + tid];
    __syncthreads();
    #pragma unroll
    for (int i = 0; i < 8; i++) {
        int lin = tid + i*256;
        int j = lin >> 7, col = lin & 127;
        float cv = g_cosT[(jg0 + j)*NPIX + n0 + col];
        float sv = g_sinT[(jg0 + j)*NPIX + n0 + col];
        float xr = qt[2*j][col], xi = qt[2*j+1][col];
        qt[2*j][col]   = cv*xr - sv*xi;
        qt[2*j+1][col] = sv*xr + cv*xi;
    }
    __syncthreads();

    int e = tid & 31;
    int grp = tid >> 5;
    int c = c0 + e;
    float wloc[9];
    #pragma unroll
    for (int i2 = 0; i2 < 9; i2++) wloc[i2] = lw[c*9 + i2];
    float lbv = lb[c];

    for (int ci = 0; ci < 16; ci++) {
        int col = grp*16 + ci;
        int n = n0 + col;
        float a1 = 0.f;
        float s2 = 0.f, cmp = 0.f, pe = 0.f;
        #pragma unroll
        for (int dd = 0; dd < 32; dd++) {
            float qv = qt[dd][col];
            a1 = fmaf(qv, kvs[dd][e], a1);
            float kmv = kms[dd];
            float p = qv * kmv;
            pe += fmaf(qv, kmv, -p);
            float yy = p - cmp;
            float tt = s2 + yy;
            cmp = (tt - s2) - yy;
            s2 = tt;
        }
        float a2 = s2 + pe;
        float z = 1.f / (a2 + 1e-6f);
        float att = a1 * z;
        int hh = n >> 6, ww2 = n & 63;
        int rbase = hh - hh0;
        float lep = lbv;
        #pragma unroll
        for (int kh = 0; kh < 3; kh++) {
            #pragma unroll
            for (int kw = 0; kw < 3; kw++) {
                int cc2 = ww2 + kw - 1;
                if (cc2 < 0 || cc2 >= 64) continue;
                lep = fmaf(wloc[kh*3 + kw], xs[rbase + kh][cc2][e], lep);
            }
        }
        out[((size_t)(b*NPIX + n))*C + c] = att + lep;
    }
}

// ---------------- launch ----------------------------------------------------
extern "C" void kernel_launch(void* const* d_in, const int* in_sizes, int n_in,
                              void* d_out, int out_size) {
    const float* x        = (const float*)d_in[0];
    const float* qk_w     = (const float*)d_in[1];
    const float* qk_b     = (const float*)d_in[2];
    const float* qsp_dw_w = (const float*)d_in[3];
    const float* qsp_dw_b = (const float*)d_in[4];
    const float* qsp_bn_g = (const float*)d_in[5];
    const float* qsp_bn_b = (const float*)d_in[6];
    const float* qsp_pw_w = (const float*)d_in[7];
    const float* qch_w    = (const float*)d_in[8];
    const float* ksp_dw_w = (const float*)d_in[9];
    const float* ksp_dw_b = (const float*)d_in[10];
    const float* ksp_bn_g = (const float*)d_in[11];
    const float* ksp_bn_b = (const float*)d_in[12];
    const float* ksp_pw_w = (const float*)d_in[13];
    const float* kch_w    = (const float*)d_in[14];
    const float* lepe_w   = (const float*)d_in[15];
    const float* lepe_b   = (const float*)d_in[16];
    const float* rope_cos = (const float*)d_in[17];
    const float* rope_sin = (const float*)d_in[18];
    float* out = (float*)d_out;

    cudaFuncSetAttribute(gemm_k, cudaFuncAttributeMaxDynamicSharedMemorySize,
                         GT_SMEM);

    split_wk<<<1024, 256>>>(qk_w);                                     // 1
    repack_rope<<<8192, 256>>>(rope_cos, rope_sin);                    // 2
    fold_misc<<<2, 512>>>(qsp_dw_w, qsp_dw_b, qsp_bn_g, qsp_bn_b,
                          ksp_dw_w, ksp_dw_b, ksp_bn_g, ksp_bn_b);     // 3
    gemm_k<<<dim3(4, 256), 512, GT_SMEM>>>(x, qk_b);                   // 4 (profile target)
    gemm_q<<<dim3(4, 256), 256>>>(x, qk_w, qk_b);                      // 5
    gate_accum<<<dim3(8, 8, B), 512>>>(0, qsp_pw_w);                   // 6
    gate_accum<<<dim3(8, 8, B), 512>>>(1, ksp_pw_w);                   // 7
    gate_finish<<<(2*B*NPIX)/256, 256>>>();                            // 8
    pool_kernel<<<dim3(C, B, 2), 256>>>();                             // 9
    chgemm<<<dim3(B, 2), 512>>>(qch_w, kch_w);                         // 10
    kv_kernel<<<dim3(HEADS, B), 256>>>(x);                             // 11
    out_kernel<<<dim3(32, HEADS, B), 256>>>(x, lepe_w, lepe_b, out);   // 12
}